// round 16
// baseline (speedup 1.0000x reference)
#include <cuda_runtime.h>
#include <cuda_bf16.h>

// Output[b,s,:] == mean(knowledge, axis=0) for every (b,s):
// top_k with max_chunks == K selects a permutation of ALL knowledge rows,
// so mean(take(knowledge, top_k), axis=1) == mean(knowledge, axis=0).
//
// R15: byte-identical resubmission of R9 measured 6.944 vs 6.624 ->
// bench noise is +/-0.3us; all variants sit on a ~5.6us launch floor
// + ~1us warm work. This round: warp-autonomous structure (zero smem,
// zero barriers) + one untried Blackwell lever: 256-bit vector stores
// (st.global.v8.f32, sm_100a+), halving store issue count. Each warp
// owns 8 float4 cols; 16 front-batched loads/thread; 2 shfl_xor finish
// the 64-row sum; 4 x STG.256 per thread, branch-free.

#define E_DIM 512
#define K_ROWS 64
#define THREADS 256
#define COLS4 (E_DIM / 4)       // 128 float4 per full row
#define COLS8 (E_DIM / 8)       // 64 float8 per full row
#define NCB 2                   // column halves
#define CB4 (COLS4 / NCB)       // 64 float4 columns per half
#define ROWS_PER_CTA 32         // 128 row-blocks x 2 col-halves = 256 CTAs

__global__ void __launch_bounds__(THREADS)
fused_mean_broadcast(const float4* __restrict__ knowledge4,
                     float* __restrict__ out) {
    int t = threadIdx.x;
    int lane = t & 31;
    int w = t >> 5;             // warp 0..7: owns float4 cols [8w, 8w+8) of the half
    int c = lane & 7;           // float4 column within warp slice
    int g = lane >> 3;          // row-group 0..3: rows [16g, 16g+16)

    int cb = blockIdx.x & (NCB - 1);   // column half 0..1
    int rb = blockIdx.x >> 1;          // row block 0..127
    int col = cb * CB4 + w * 8 + c;    // global float4 column

    // 16 independent front-batched loads (warp load = 8 full 128B sectors).
    float4 s = make_float4(0.f, 0.f, 0.f, 0.f);
#pragma unroll
    for (int k = 0; k < K_ROWS / 4; ++k) {
        float4 a = knowledge4[(g * (K_ROWS / 4) + k) * COLS4 + col];
        s.x += a.x; s.y += a.y; s.z += a.z; s.w += a.w;
    }

    // Lanes with equal c differ only in the g bits (3,4): two xor
    // shuffles complete the 64-row column sum. No smem, no barrier.
#pragma unroll
    for (int d = 8; d <= 16; d <<= 1) {
        s.x += __shfl_xor_sync(0xffffffffu, s.x, d);
        s.y += __shfl_xor_sync(0xffffffffu, s.y, d);
        s.z += __shfl_xor_sync(0xffffffffu, s.z, d);
        s.w += __shfl_xor_sync(0xffffffffu, s.w, d);
    }
    const float inv = 1.0f / (float)K_ROWS;
    s.x *= inv; s.y *= inv; s.z *= inv; s.w *= inv;

    // Pair lanes to form a 256-bit value: even c lanes hold the low
    // float4, odd c lanes the high float4 of a float8. Each even-c lane
    // fetches its neighbor's float4 via shfl and issues STG.256.
    float4 hi;
    hi.x = __shfl_xor_sync(0xffffffffu, s.x, 1);
    hi.y = __shfl_xor_sync(0xffffffffu, s.y, 1);
    hi.z = __shfl_xor_sync(0xffffffffu, s.z, 1);
    hi.w = __shfl_xor_sync(0xffffffffu, s.w, 1);

    // CTA writes rows [rb*32, +32) of its column half; replica-group g
    // writes 8 rows. 16 active lanes/warp x STG.256 = 4 x 128B sectors.
    if ((c & 1) == 0) {
        int col8 = (cb * CB4 + w * 8 + c) >> 1;   // global float8 column
        int r0 = rb * ROWS_PER_CTA + g * (ROWS_PER_CTA / 4);
#pragma unroll
        for (int r = 0; r < ROWS_PER_CTA / 4; ++r) {
            float* p = out + ((size_t)(r0 + r) * COLS8 + col8) * 8;
            asm volatile(
                "st.global.v8.f32 [%0], {%1, %2, %3, %4, %5, %6, %7, %8};"
                :: "l"(p),
                   "f"(s.x), "f"(s.y), "f"(s.z), "f"(s.w),
                   "f"(hi.x), "f"(hi.y), "f"(hi.z), "f"(hi.w)
                : "memory");
        }
    }
}

extern "C" void kernel_launch(void* const* d_in, const int* in_sizes, int n_in,
                              void* d_out, int out_size) {
    // d_in[0]: query_embedding [4,1024,512] f32 (unused — output is query-independent)
    // d_in[1]: knowledge [64,512] f32
    const float* knowledge = (const float*)d_in[1];
    float* out = (float*)d_out;

    int rows = out_size / E_DIM;                 // 4096
    int blocks = NCB * (rows / ROWS_PER_CTA);    // 256

    fused_mean_broadcast<<<blocks, THREADS>>>(
        reinterpret_cast<const float4*>(knowledge), out);
}